// round 15
// baseline (speedup 1.0000x reference)
#include <cuda_runtime.h>
#include <cuda_fp16.h>
#include <math.h>
#include <stdint.h>

#define Bc 16
#define Sc 512
#define Dc 1024
#define Hc 8
#define DFFc 4096
#define DKc 128
#define MROWS (Bc*Sc)
#define NEGF (-1e32f)

// ---------------- scratch ----------------
__device__ __half g_wk_h[(size_t)3*Dc*Dc];
__device__ __half g_wv_h[(size_t)3*Dc*Dc];
__device__ __half g_wo_h[(size_t)3*Dc*Dc];
__device__ __half g_w1_h[(size_t)3*DFFc*Dc];
__device__ __half g_w2_h[(size_t)3*Dc*DFFc];
__device__ __half g_qa_h[(size_t)MROWS*Dc];
__device__ __half g_q_h[(size_t)MROWS*Dc];
__device__ float  g_y[(size_t)MROWS*Dc];
__device__ __half g_y_h[(size_t)MROWS*Dc];
__device__ float  g_xb[(size_t)MROWS*Dc];
__device__ __half g_xb_h[(size_t)MROWS*Dc];
__device__ float  g_t1[(size_t)MROWS*Dc];
__device__ __half g_t1_h[(size_t)MROWS*Dc];
// buffer set A (layers 0,2)
__device__ __half g_cat_h[(size_t)MROWS*Dc];
__device__ float  g_proj[(size_t)MROWS*Dc];
__device__ __half g_qk_h[(size_t)MROWS*Dc];
__device__ __half g_v_h[(size_t)MROWS*Dc];
__device__ float  g_scores[(size_t)Bc*Hc*Sc*Sc];
__device__ __half g_scores_h[(size_t)Bc*Hc*Sc*Sc];
__device__ int    g_ext[Hc*Sc];
// buffer set B (layer 1, concurrent)
__device__ __half g_cat2_h[(size_t)MROWS*Dc];
__device__ float  g_proj2[(size_t)MROWS*Dc];
__device__ __half g_qk2_h[(size_t)MROWS*Dc];
__device__ __half g_v2_h[(size_t)MROWS*Dc];
__device__ float  g_scores2[(size_t)Bc*Hc*Sc*Sc];
__device__ __half g_scores2_h[(size_t)Bc*Hc*Sc*Sc];
__device__ int    g_ext2[Hc*Sc];
__device__ __half g_ff_h[(size_t)MROWS*DFFc];

__device__ __forceinline__ void cp16(uint32_t dst, const void* src) {
    asm volatile("cp.async.cg.shared.global [%0], [%1], 16;" :: "r"(dst), "l"(src));
}
#define SWZ64(x) ((x) ^ (((x) >> 3) & 0x30))

// ---- fp16 tensor GEMM: C = alpha*A(M,K)@B(N,K)^T + bias.
// CTA tile 128x128, BK=32, 4 warps (64x64), 4-stage cp.async, ONE sync/iter.
// mode: 0=float flat, 1=half flat, 2=half [B,H,S,DK] heads,
//       3=half (B,S,D) att concat + causal K-limit
__global__ __launch_bounds__(128, 2)
void gemm_h(const __half* __restrict__ A, const __half* __restrict__ Bm,
            const float* __restrict__ bias, void* __restrict__ Cv,
            int N, int K, long sA, long sB, long sC,
            float alpha, int relu, int mode)
{
    extern __shared__ __half sm[];
    const int tid = threadIdx.x, warp = tid >> 5, lane = tid & 31;
    const int wm = warp >> 1, wn = warp & 1;

    const __half* Ab = A + blockIdx.z * sA + (long)blockIdx.y * 128 * K;
    const __half* Bb = Bm + blockIdx.z * sB + (long)blockIdx.x * 128 * K;

    float acc[4][8][4];
#pragma unroll
    for (int t = 0; t < 4; t++)
#pragma unroll
        for (int u = 0; u < 8; u++)
#pragma unroll
            for (int r = 0; r < 4; r++) acc[t][u][r] = 0.f;

    const uint32_t base = (uint32_t)__cvta_generic_to_shared(sm);
    // stage s: A at base + s*16384 (8KB), B at +8192
    auto ld_stage = [&](int s, int k0) {
        uint32_t ab = base + s * 16384, bb = ab + 8192;
#pragma unroll
        for (int q = 0; q < 4; q++) {
            int idx = q * 128 + tid;
            int row = idx >> 2, c = idx & 3;
            uint32_t off = SWZ64((uint32_t)(row * 64 + c * 16));
            long gofs = (long)row * K + k0 + c * 8;
            cp16(ab + off, Ab + gofs);
            cp16(bb + off, Bb + gofs);
        }
        asm volatile("cp.async.commit_group;" ::: "memory");
    };

    const int niter = (mode == 3) ? (int)(blockIdx.y + 1) * 4 : (K >> 5);

    // prologue: 3 stages in flight (k=0,32,64 always within smallest K=128)
    ld_stage(0, 0);
    ld_stage(1, 32);
    ld_stage(2, 64);

    for (int it = 0; it < niter; ++it) {
        if (it + 2 < niter)      asm volatile("cp.async.wait_group 2;" ::: "memory");
        else if (it + 1 < niter) asm volatile("cp.async.wait_group 1;" ::: "memory");
        else                     asm volatile("cp.async.wait_group 0;" ::: "memory");
        __syncthreads();

        // issue next load first (slot (it+3)&3 was computed at it-1; sync retired it)
        if (it + 3 < niter) ld_stage((it + 3) & 3, (it + 3) << 5);

        uint32_t ab = base + (it & 3) * 16384, bb = ab + 8192;
#pragma unroll
        for (int ks = 0; ks < 2; ks++) {
            uint32_t af[4][4], bf[8][2];
#pragma unroll
            for (int t = 0; t < 4; t++) {
                int row = wm * 64 + t * 16 + (lane & 15);
                int ch = ks * 2 + (lane >> 4);
                uint32_t ad = ab + SWZ64((uint32_t)(row * 64 + ch * 16));
                asm volatile(
                    "ldmatrix.sync.aligned.m8n8.x4.shared.b16 {%0,%1,%2,%3}, [%4];"
                    : "=r"(af[t][0]), "=r"(af[t][1]), "=r"(af[t][2]), "=r"(af[t][3])
                    : "r"(ad));
            }
#pragma unroll
            for (int p = 0; p < 4; p++) {
                int nrow = wn * 64 + p * 16 + ((lane >> 4) & 1) * 8 + (lane & 7);
                int ch = ks * 2 + ((lane >> 3) & 1);
                uint32_t bd = bb + SWZ64((uint32_t)(nrow * 64 + ch * 16));
                asm volatile(
                    "ldmatrix.sync.aligned.m8n8.x4.shared.b16 {%0,%1,%2,%3}, [%4];"
                    : "=r"(bf[2*p][0]), "=r"(bf[2*p][1]),
                      "=r"(bf[2*p+1][0]), "=r"(bf[2*p+1][1])
                    : "r"(bd));
            }
#pragma unroll
            for (int t = 0; t < 4; t++)
#pragma unroll
                for (int u = 0; u < 8; u++) {
                    asm volatile(
                        "mma.sync.aligned.m16n8k16.row.col.f32.f16.f16.f32 "
                        "{%0,%1,%2,%3}, {%4,%5,%6,%7}, {%8,%9}, {%0,%1,%2,%3};"
                        : "+f"(acc[t][u][0]), "+f"(acc[t][u][1]),
                          "+f"(acc[t][u][2]), "+f"(acc[t][u][3])
                        : "r"(af[t][0]), "r"(af[t][1]), "r"(af[t][2]), "r"(af[t][3]),
                          "r"(bf[u][0]), "r"(bf[u][1]));
                }
        }
    }

    const int rb0 = blockIdx.y * 128 + wm * 64;
    const int cb0 = blockIdx.x * 128 + wn * 64;
    const int rsub = lane >> 2, csub = (lane & 3) * 2;
#pragma unroll
    for (int t = 0; t < 4; t++) {
        int r0 = rb0 + t * 16 + rsub;
#pragma unroll
        for (int u = 0; u < 8; u++) {
            int col = cb0 + u * 8 + csub;
            float b0 = 0.f, b1 = 0.f;
            if (bias) { b0 = bias[col]; b1 = bias[col + 1]; }
            float v0 = acc[t][u][0] * alpha + b0;
            float v1 = acc[t][u][1] * alpha + b1;
            float v2 = acc[t][u][2] * alpha + b0;
            float v3 = acc[t][u][3] * alpha + b1;
            if (relu) {
                v0 = fmaxf(v0, 0.f); v1 = fmaxf(v1, 0.f);
                v2 = fmaxf(v2, 0.f); v3 = fmaxf(v3, 0.f);
            }
            if (mode == 0) {
                float* Cf = (float*)Cv + blockIdx.z * sC;
                *(float2*)(Cf + (long)r0 * N + col)       = make_float2(v0, v1);
                *(float2*)(Cf + (long)(r0 + 8) * N + col) = make_float2(v2, v3);
            } else if (mode == 1) {
                __half* Ch = (__half*)Cv + blockIdx.z * sC;
                *(__half2*)(Ch + (long)r0 * N + col)       = __floats2half2_rn(v0, v1);
                *(__half2*)(Ch + (long)(r0 + 8) * N + col) = __floats2half2_rn(v2, v3);
            } else if (mode == 2) {
                int h = col >> 7, dk = col & 127;
                __half* Ch = (__half*)Cv;
                {
                    int b = r0 >> 9, ss = r0 & 511;
                    *(__half2*)(Ch + (((long)(b*Hc + h)*Sc + ss)*DKc + dk)) =
                        __floats2half2_rn(v0, v1);
                }
                {
                    int r1 = r0 + 8;
                    int b = r1 >> 9, ss = r1 & 511;
                    *(__half2*)(Ch + (((long)(b*Hc + h)*Sc + ss)*DKc + dk)) =
                        __floats2half2_rn(v2, v3);
                }
            } else {
                int z = blockIdx.z;
                int b = z >> 3, h = z & 7;
                __half* Ch = (__half*)Cv;
                *(__half2*)(Ch + (((long)(b*Sc + r0))*Dc + h*DKc + col)) =
                    __floats2half2_rn(v0, v1);
                *(__half2*)(Ch + (((long)(b*Sc + r0 + 8))*Dc + h*DKc + col)) =
                    __floats2half2_rn(v2, v3);
            }
        }
    }
}

// ---------------- conversions ----------------
__global__ void round_copy3(const float* __restrict__ i0, __half* __restrict__ o0,
                            const float* __restrict__ i1, __half* __restrict__ o1,
                            const float* __restrict__ i2, __half* __restrict__ o2,
                            long n4)
{
    long t = (long)blockIdx.x * blockDim.x + threadIdx.x;
    if (t >= n4) return;
    const float* in; __half* out;
    if (blockIdx.y == 0)      { in = i0; out = o0; }
    else if (blockIdx.y == 1) { in = i1; out = o1; }
    else                      { in = i2; out = o2; }
    float4 v = ((const float4*)in)[t];
    __half2 h0 = __floats2half2_rn(v.x, v.y);
    __half2 h1 = __floats2half2_rn(v.z, v.w);
    *(uint2*)(out + t * 4) = make_uint2(*(uint32_t*)&h0, *(uint32_t*)&h1);
}

__global__ void round_copy2(const float* __restrict__ i0, __half* __restrict__ o0,
                            const float* __restrict__ i1, __half* __restrict__ o1,
                            long n4)
{
    long t = (long)blockIdx.x * blockDim.x + threadIdx.x;
    if (t >= n4) return;
    const float* in = blockIdx.y ? i1 : i0;
    __half* out = blockIdx.y ? o1 : o0;
    float4 v = ((const float4*)in)[t];
    __half2 h0 = __floats2half2_rn(v.x, v.y);
    __half2 h1 = __floats2half2_rn(v.z, v.w);
    *(uint2*)(out + t * 4) = make_uint2(*(uint32_t*)&h0, *(uint32_t*)&h1);
}

__global__ void round_copy_h(const float* __restrict__ in, __half* __restrict__ out, long n4)
{
    long t = (long)blockIdx.x * blockDim.x + threadIdx.x;
    if (t < n4) {
        float4 v = ((const float4*)in)[t];
        __half2 h0 = __floats2half2_rn(v.x, v.y);
        __half2 h1 = __floats2half2_rn(v.z, v.w);
        *(uint2*)(out + t * 4) = make_uint2(*(uint32_t*)&h0, *(uint32_t*)&h1);
    }
}

// (B,S,D) half -> (B,H,DK,S) half
__global__ void to_heads_t_h(const __half* __restrict__ in, __half* __restrict__ out)
{
    int t = blockIdx.x * blockDim.x + threadIdx.x;
    int s = t & (Sc - 1);
    int rest = t >> 9;
    int dq = rest & 31;
    rest >>= 5;
    int h = rest & 7;
    int b = rest >> 3;
    uint2 u = *(const uint2*)(in + ((long)(b*Sc + s) * Dc + h*DKc + dq*4));
    __half2 h0 = *(__half2*)&u.x;
    __half2 h1 = *(__half2*)&u.y;
    long ob = ((long)((b*Hc + h)*DKc) + dq*4) * Sc + s;
    out[ob]        = __low2half(h0);
    out[ob + Sc]   = __high2half(h0);
    out[ob + 2*Sc] = __low2half(h1);
    out[ob + 3*Sc] = __high2half(h1);
}

__global__ void compute_ext(const float* __restrict__ alphas, const float* __restrict__ E,
                            int* __restrict__ ext)
{
    int idx = blockIdx.x * blockDim.x + threadIdx.x;
    if (idx < Hc * Sc) {
        float a0 = alphas[idx*2], a1 = alphas[idx*2+1];
        float g0 = -logf(E[idx*2] + 1e-5f), g1 = -logf(E[idx*2+1] + 1e-5f);
        ext[idx] = ((a0 + g0) < (a1 + g1)) ? 1 : 0;
    }
}

// ---------------- warp-per-row fused softmax pipeline ----------------
__global__ __launch_bounds__(256)
void attn_softmax2(const float* __restrict__ scores, __half* __restrict__ out_h,
                   const int* __restrict__ ext, const float* __restrict__ gam,
                   int bmask, int zero_pad)
{
    const int warp = threadIdx.x >> 5, lane = threadIdx.x & 31;
    const long rid = (long)blockIdx.x * 8 + warp;
    const int i = (int)(rid & (Sc - 1));
    const int h = (int)((rid >> 9) & (Hc - 1));
    const float* row = scores + rid * Sc;
    const int j0 = lane * 16;

    float raw[16];
#pragma unroll
    for (int c = 0; c < 4; c++)
        *(float4*)&raw[c*4] = *(const float4*)(row + j0 + c*4);

    float g = gam[h];
    float sp = (g > 20.f) ? g : log1pf(expf(g));
    const int* exth = ext + h * Sc;

    float m1 = NEGF, v1[16];
#pragma unroll
    for (int c = 0; c < 16; c++) {
        int j = j0 + c;
        int d = j - i; d = d < 0 ? -d : d;
        bool causal = j < i + bmask;
        bool dam = causal || (exth[d] != 0);
        v1[c] = dam ? raw[c] : NEGF;
        m1 = fmaxf(m1, v1[c]);
    }
#pragma unroll
    for (int o = 16; o; o >>= 1) m1 = fmaxf(m1, __shfl_xor_sync(~0u, m1, o));
    float s1 = 0.f, p[16];
#pragma unroll
    for (int c = 0; c < 16; c++) { p[c] = expf(v1[c] - m1); s1 += p[c]; }
#pragma unroll
    for (int o = 16; o; o >>= 1) s1 += __shfl_xor_sync(~0u, s1, o);
    float inv1 = 1.f / s1;

    float run = 0.f, cum[16];
#pragma unroll
    for (int c = 0; c < 16; c++) {
        int j = j0 + c;
        float sc = (j < i + bmask) ? p[c] * inv1 : 0.f;
        run += sc;
        cum[c] = run;
    }
    float excl = run;
#pragma unroll
    for (int o = 1; o < 32; o <<= 1) {
        float t = __shfl_up_sync(~0u, excl, o);
        if (lane >= o) excl += t;
    }
    float tot = __shfl_sync(~0u, excl, 31);
    excl -= run;

    float m2 = NEGF, v2[16];
#pragma unroll
    for (int c = 0; c < 16; c++) {
        int j = j0 + c;
        int d = j - i; d = d < 0 ? -d : d;
        bool causal = j < i + bmask;
        float rem = tot - (excl + cum[c]);
        float dist = sqrtf(fmaxf(rem * (float)d, 0.f));
        float te = expf(dist * (-sp));
        te = fminf(fmaxf(te, 1e-5f), 1e5f);
        v2[c] = causal ? raw[c] * te : NEGF;
        m2 = fmaxf(m2, v2[c]);
    }
#pragma unroll
    for (int o = 16; o; o >>= 1) m2 = fmaxf(m2, __shfl_xor_sync(~0u, m2, o));
    float s2 = 0.f;
#pragma unroll
    for (int c = 0; c < 16; c++) { v2[c] = expf(v2[c] - m2); s2 += v2[c]; }
#pragma unroll
    for (int o = 16; o; o >>= 1) s2 += __shfl_xor_sync(~0u, s2, o);
    float inv2 = 1.f / s2;

    bool zp = (zero_pad && i == 0);
    uint32_t w[8];
#pragma unroll
    for (int c = 0; c < 8; c++) {
        float a = zp ? 0.f : v2[2*c] * inv2;
        float b = zp ? 0.f : v2[2*c+1] * inv2;
        __half2 hh = __floats2half2_rn(a, b);
        w[c] = *(uint32_t*)&hh;
    }
    __half* orow = out_h + rid * Sc + j0;
    *(uint4*)(orow)     = make_uint4(w[0], w[1], w[2], w[3]);
    *(uint4*)(orow + 8) = make_uint4(w[4], w[5], w[6], w[7]);
}

// ---------------- residual + layernorm ----------------
__global__ __launch_bounds__(256)
void add_ln(const float* __restrict__ a, const float* __restrict__ c,
            const float* __restrict__ g, const float* __restrict__ bt,
            float* __restrict__ out, __half* __restrict__ out_h)
{
    const int r = blockIdx.x;
    const long base = (long)r * Dc;
    __shared__ float red[256];
    float vals[4];
    float s = 0.f;
#pragma unroll
    for (int q = 0; q < 4; q++) {
        int ci = threadIdx.x + q * 256;
        vals[q] = a[base + ci] + c[base + ci];
        s += vals[q];
    }
    red[threadIdx.x] = s; __syncthreads();
    for (int off = 128; off; off >>= 1) {
        if (threadIdx.x < off) red[threadIdx.x] += red[threadIdx.x + off];
        __syncthreads();
    }
    float mu = red[0] * (1.f / Dc); __syncthreads();
    float vs = 0.f;
#pragma unroll
    for (int q = 0; q < 4; q++) { float d = vals[q] - mu; vs += d * d; }
    red[threadIdx.x] = vs; __syncthreads();
    for (int off = 128; off; off >>= 1) {
        if (threadIdx.x < off) red[threadIdx.x] += red[threadIdx.x + off];
        __syncthreads();
    }
    float inv = rsqrtf(red[0] * (1.f / Dc) + 1e-5f);
#pragma unroll
    for (int q = 0; q < 4; q++) {
        int ci = threadIdx.x + q * 256;
        float o = (vals[q] - mu) * inv * g[ci] + bt[ci];
        out[base + ci] = o;
        if (out_h) out_h[base + ci] = __float2half_rn(o);
    }
}

// ---------------- host orchestration ----------------
struct LayerBufs {
    __half *qk_h, *v_h, *cat_h, *scores_h;
    float *scores, *proj;
    int* ext;
};
struct Weights {
    __half *wk, *wv, *wo, *w1, *w2;
};

#define GEMM_SMEM 65536

static void vprep(const __half* Vin_h, int l, const float* vb,
                  const Weights& W, const LayerBufs& S, cudaStream_t st)
{
    const long DD = (long)Dc * Dc;
    gemm_h<<<dim3(Dc/128, MROWS/128), 128, GEMM_SMEM, st>>>(
        Vin_h, W.wv + (long)l*DD, vb + (long)l*Dc, S.cat_h, Dc, Dc, 0, 0, 0, 1.f, 0, 1);
    to_heads_t_h<<<(MROWS*Dc/4)/256, 256, 0, st>>>(S.cat_h, S.v_h);
}

static void layer_core(const float* X, const __half* X_h,
                       float* outbuf, __half* outbuf_h,
                       float* t1, __half* t1_h, __half* ff_h,
                       int l, int bmask, int apply_pos,
                       const float* kb, const float* ob,
                       const float* gammas, const float* alphas, const float* gE,
                       const float* ln1g, const float* ln1b,
                       const float* b1, const float* b2,
                       const float* ln2g, const float* ln2b,
                       const Weights& W, const LayerBufs& S,
                       cudaStream_t st, cudaEvent_t evV, cudaEvent_t evFF)
{
    const long DD = (long)Dc * Dc;
    const float scl = 1.0f / sqrtf((float)DKc);
    const long SDK = (long)Sc * DKc;
    const long SS = (long)Sc * Sc;

    float*  ln1o   = apply_pos ? t1   : outbuf;
    __half* ln1o_h = apply_pos ? t1_h : outbuf_h;

    gemm_h<<<dim3(Dc/128, MROWS/128), 128, GEMM_SMEM, st>>>(
        X_h, W.wk + (long)l*DD, kb + (long)l*Dc, S.qk_h, Dc, Dc, 0, 0, 0, 1.f, 0, 2);
    gemm_h<<<dim3(Sc/128, Sc/128, Bc*Hc), 128, GEMM_SMEM, st>>>(
        S.qk_h, S.qk_h, nullptr, S.scores, Sc, DKc, SDK, SDK, SS, scl, 0, 0);
    compute_ext<<<(Hc*Sc + 255)/256, 256, 0, st>>>(alphas + (long)l*Hc*Sc*2,
                                                   gE + (long)l*Hc*Sc*2, S.ext);
    attn_softmax2<<<(Bc*Hc*Sc)/8, 256, 0, st>>>(S.scores, S.scores_h, S.ext,
                                                gammas + (long)l*Hc, bmask, bmask == 0);
    if (evV) cudaStreamWaitEvent(st, evV, 0);
    gemm_h<<<dim3(1, Sc/128, Bc*Hc), 128, GEMM_SMEM, st>>>(
        S.scores_h, S.v_h, nullptr, S.cat_h, DKc, Sc, SS, SDK, 0, 1.f, 0, 3);
    gemm_h<<<dim3(Dc/128, MROWS/128), 128, GEMM_SMEM, st>>>(
        S.cat_h, W.wo + (long)l*DD, ob + (long)l*Dc, S.proj, Dc, Dc, 0, 0, 0, 1.f, 0, 0);
    add_ln<<<MROWS, 256, 0, st>>>(X, S.proj, ln1g + (long)l*Dc, ln1b + (long)l*Dc,
                                  ln1o, ln1o_h);

    if (apply_pos) {
        if (evFF) cudaStreamWaitEvent(st, evFF, 0);
        gemm_h<<<dim3(DFFc/128, MROWS/128), 128, GEMM_SMEM, st>>>(
            t1_h, W.w1 + (long)l*DFFc*Dc, b1 + (long)l*DFFc, ff_h,
            DFFc, Dc, 0, 0, 0, 1.f, 1, 1);
        gemm_h<<<dim3(Dc/128, MROWS/128), 128, GEMM_SMEM, st>>>(
            ff_h, W.w2 + (long)l*Dc*DFFc, b2 + (long)l*Dc, S.proj,
            Dc, DFFc, 0, 0, 0, 1.f, 0, 0);
        add_ln<<<MROWS, 256, 0, st>>>(t1, S.proj, ln2g + (long)l*Dc, ln2b + (long)l*Dc,
                                      outbuf, outbuf_h);
    }
}

extern "C" void kernel_launch(void* const* d_in, const int* in_sizes, int n_in,
                              void* d_out, int out_size)
{
    const float* q_embed  = (const float*)d_in[0];
    const float* qa_embed = (const float*)d_in[1];
    const float* kW = (const float*)d_in[2];
    const float* kb = (const float*)d_in[3];
    const float* vW = (const float*)d_in[4];
    const float* vb = (const float*)d_in[5];
    const float* oW = (const float*)d_in[6];
    const float* ob = (const float*)d_in[7];
    const float* gammas = (const float*)d_in[8];
    const float* alphas = (const float*)d_in[9];
    const float* ln1g = (const float*)d_in[10];
    const float* ln1b = (const float*)d_in[11];
    const float* w1 = (const float*)d_in[12];
    const float* b1 = (const float*)d_in[13];
    const float* w2 = (const float*)d_in[14];
    const float* b2 = (const float*)d_in[15];
    const float* ln2g = (const float*)d_in[16];
    const float* ln2b = (const float*)d_in[17];
    const float* gE = (const float*)d_in[18];
    float* out = (float*)d_out;

    Weights W;
    cudaGetSymbolAddress((void**)&W.wk, g_wk_h);
    cudaGetSymbolAddress((void**)&W.wv, g_wv_h);
    cudaGetSymbolAddress((void**)&W.wo, g_wo_h);
    cudaGetSymbolAddress((void**)&W.w1, g_w1_h);
    cudaGetSymbolAddress((void**)&W.w2, g_w2_h);

    LayerBufs A, B2;
    cudaGetSymbolAddress((void**)&A.qk_h, g_qk_h);
    cudaGetSymbolAddress((void**)&A.v_h, g_v_h);
    cudaGetSymbolAddress((void**)&A.cat_h, g_cat_h);
    cudaGetSymbolAddress((void**)&A.scores, g_scores);
    cudaGetSymbolAddress((void**)&A.scores_h, g_scores_h);
    cudaGetSymbolAddress((void**)&A.proj, g_proj);
    cudaGetSymbolAddress((void**)&A.ext, g_ext);
    cudaGetSymbolAddress((void**)&B2.qk_h, g_qk2_h);
    cudaGetSymbolAddress((void**)&B2.v_h, g_v2_h);
    cudaGetSymbolAddress((void**)&B2.cat_h, g_cat2_h);
    cudaGetSymbolAddress((void**)&B2.scores, g_scores2);
    cudaGetSymbolAddress((void**)&B2.scores_h, g_scores2_h);
    cudaGetSymbolAddress((void**)&B2.proj, g_proj2);
    cudaGetSymbolAddress((void**)&B2.ext, g_ext2);

    __half *qa_h, *q_h, *y_h, *xb_h, *t1_h, *ff_h;
    float *y, *xb, *t1;
    cudaGetSymbolAddress((void**)&qa_h, g_qa_h);
    cudaGetSymbolAddress((void**)&q_h, g_q_h);
    cudaGetSymbolAddress((void**)&y, g_y);
    cudaGetSymbolAddress((void**)&y_h, g_y_h);
    cudaGetSymbolAddress((void**)&xb, g_xb);
    cudaGetSymbolAddress((void**)&xb_h, g_xb_h);
    cudaGetSymbolAddress((void**)&t1, g_t1);
    cudaGetSymbolAddress((void**)&t1_h, g_t1_h);
    cudaGetSymbolAddress((void**)&ff_h, g_ff_h);

    cudaFuncSetAttribute(gemm_h, cudaFuncAttributeMaxDynamicSharedMemorySize, GEMM_SMEM);

    cudaStream_t s2;
    cudaStreamCreateWithFlags(&s2, cudaStreamNonBlocking);
    cudaEvent_t eFork, eW, eQA, eFF, eV0, eL1, eY, eV2, eJoin;
    cudaEventCreateWithFlags(&eFork, cudaEventDisableTiming);
    cudaEventCreateWithFlags(&eW, cudaEventDisableTiming);
    cudaEventCreateWithFlags(&eQA, cudaEventDisableTiming);
    cudaEventCreateWithFlags(&eFF, cudaEventDisableTiming);
    cudaEventCreateWithFlags(&eV0, cudaEventDisableTiming);
    cudaEventCreateWithFlags(&eL1, cudaEventDisableTiming);
    cudaEventCreateWithFlags(&eY, cudaEventDisableTiming);
    cudaEventCreateWithFlags(&eV2, cudaEventDisableTiming);
    cudaEventCreateWithFlags(&eJoin, cudaEventDisableTiming);

    long nDD4 = (long)3 * Dc * Dc / 4;
    long nFF4 = (long)3 * DFFc * Dc / 4;
    long nX4  = (long)MROWS * Dc / 4;

    cudaEventRecord(eFork, 0);
    cudaStreamWaitEvent(s2, eFork, 0);

    round_copy3<<<dim3((unsigned)((nDD4 + 255) / 256), 3), 256>>>(
        kW, W.wk, vW, W.wv, oW, W.wo, nDD4);
    cudaEventRecord(eW, 0);
    round_copy_h<<<(int)((nX4 + 255) / 256), 256>>>(qa_embed, qa_h, nX4);
    cudaEventRecord(eQA, 0);

    round_copy2<<<dim3((unsigned)((nFF4 + 255) / 256), 2), 256, 0, s2>>>(
        w1, W.w1, w2, W.w2, nFF4);
    cudaEventRecord(eFF, s2);
    round_copy_h<<<(int)((nX4 + 255) / 256), 256, 0, s2>>>(q_embed, q_h, nX4);
    cudaStreamWaitEvent(s2, eW, 0);
    cudaStreamWaitEvent(s2, eQA, 0);
    vprep(qa_h, 0, vb, W, A, s2);
    cudaEventRecord(eV0, s2);

    layer_core(qa_embed, qa_h, y, y_h, t1, t1_h, ff_h, 0, 1, 1,
               kb, ob, gammas, alphas, gE, ln1g, ln1b, b1, b2, ln2g, ln2b,
               W, A, 0, eV0, eFF);
    cudaEventRecord(eY, 0);

    vprep(q_h, 1, vb, W, B2, s2);
    layer_core(q_embed, q_h, xb, xb_h, nullptr, nullptr, nullptr, 1, 1, 0,
               kb, ob, gammas, alphas, gE, ln1g, ln1b, b1, b2, ln2g, ln2b,
               W, B2, s2, nullptr, nullptr);
    cudaEventRecord(eL1, s2);

    cudaStreamWaitEvent(s2, eY, 0);
    vprep(y_h, 2, vb, W, A, s2);
    cudaEventRecord(eV2, s2);

    cudaStreamWaitEvent(0, eL1, 0);
    layer_core(xb, xb_h, out, nullptr, t1, t1_h, ff_h, 2, 0, 1,
               kb, ob, gammas, alphas, gE, ln1g, ln1b, b1, b2, ln2g, ln2b,
               W, A, 0, eV2, nullptr);

    cudaEventRecord(eJoin, s2);
    cudaStreamWaitEvent(0, eJoin, 0);
}

// round 16
// speedup vs baseline: 1.0218x; 1.0218x over previous
#include <cuda_runtime.h>
#include <cuda_fp16.h>
#include <math.h>
#include <stdint.h>

#define Bc 16
#define Sc 512
#define Dc 1024
#define Hc 8
#define DFFc 4096
#define DKc 128
#define MROWS (Bc*Sc)
#define NEGF (-1e32f)

// ---------------- scratch ----------------
__device__ __half g_wk_h[(size_t)3*Dc*Dc];
__device__ __half g_wv_h[(size_t)3*Dc*Dc];
__device__ __half g_wo_h[(size_t)3*Dc*Dc];
__device__ __half g_w1_h[(size_t)3*DFFc*Dc];
__device__ __half g_w2_h[(size_t)3*Dc*DFFc];
__device__ __half g_qa_h[(size_t)MROWS*Dc];
__device__ __half g_q_h[(size_t)MROWS*Dc];
__device__ float  g_y[(size_t)MROWS*Dc];
__device__ __half g_y_h[(size_t)MROWS*Dc];
__device__ float  g_xb[(size_t)MROWS*Dc];
__device__ __half g_xb_h[(size_t)MROWS*Dc];
__device__ float  g_t1[(size_t)MROWS*Dc];
__device__ __half g_t1_h[(size_t)MROWS*Dc];
// buffer set A (layers 0,2)
__device__ __half g_cat_h[(size_t)MROWS*Dc];
__device__ float  g_proj[(size_t)MROWS*Dc];
__device__ __half g_qk_h[(size_t)MROWS*Dc];
__device__ __half g_v_h[(size_t)MROWS*Dc];
__device__ float  g_scores[(size_t)Bc*Hc*Sc*Sc];
__device__ __half g_scores_h[(size_t)Bc*Hc*Sc*Sc];
__device__ int    g_ext[Hc*Sc];
// buffer set B (layer 1, concurrent)
__device__ __half g_cat2_h[(size_t)MROWS*Dc];
__device__ float  g_proj2[(size_t)MROWS*Dc];
__device__ __half g_qk2_h[(size_t)MROWS*Dc];
__device__ __half g_v2_h[(size_t)MROWS*Dc];
__device__ float  g_scores2[(size_t)Bc*Hc*Sc*Sc];
__device__ __half g_scores2_h[(size_t)Bc*Hc*Sc*Sc];
__device__ int    g_ext2[Hc*Sc];
__device__ __half g_ff_h[(size_t)MROWS*DFFc];

__device__ __forceinline__ void cp16(uint32_t dst, const void* src) {
    asm volatile("cp.async.cg.shared.global [%0], [%1], 16;" :: "r"(dst), "l"(src));
}
#define SWZ128(x) ((x) ^ (((x) >> 3) & 0x70))

// ---- fp16 tensor GEMM: C = alpha*A(M,K)@B(N,K)^T + bias.
// CTA tile 128x128, BK=64, 128 threads (4 warps 2x2, 64x64), 2-stage cp.async.
// mode: 0=float flat, 1=half flat, 2=half [B,H,S,DK] heads,
//       3=half (B,S,D) att concat + causal K-limit (heavy tiles first)
__global__ __launch_bounds__(128, 2)
void gemm_h(const __half* __restrict__ A, const __half* __restrict__ Bm,
            const float* __restrict__ bias, void* __restrict__ Cv,
            int N, int K, long sA, long sB, long sC,
            float alpha, int relu, int mode)
{
    extern __shared__ __half sm[];
    const int tid = threadIdx.x, warp = tid >> 5, lane = tid & 31;
    const int wm = warp >> 1, wn = warp & 1;

    // mode 3: reverse row-tile order so heavy (long-K) tiles launch first
    const int ytile = (mode == 3) ? (int)(gridDim.y - 1 - blockIdx.y) : (int)blockIdx.y;

    const __half* Ab = A + blockIdx.z * sA + (long)ytile * 128 * K;
    const __half* Bb = Bm + blockIdx.z * sB + (long)blockIdx.x * 128 * K;

    float acc[4][8][4];
#pragma unroll
    for (int t = 0; t < 4; t++)
#pragma unroll
        for (int u = 0; u < 8; u++)
#pragma unroll
            for (int r = 0; r < 4; r++) acc[t][u][r] = 0.f;

    const uint32_t base = (uint32_t)__cvta_generic_to_shared(sm);
    auto ld_stage = [&](int s, int k0) {
        uint32_t ab = base + s * 32768, bb = ab + 16384;
#pragma unroll
        for (int q = 0; q < 8; q++) {
            int idx = q * 128 + tid;
            int row = idx >> 3, c = idx & 7;
            uint32_t off = SWZ128((uint32_t)(row * 128 + c * 16));
            long gofs = (long)row * K + k0 + c * 8;
            cp16(ab + off, Ab + gofs);
            cp16(bb + off, Bb + gofs);
        }
        asm volatile("cp.async.commit_group;" ::: "memory");
    };

    const int niter = (mode == 3) ? (ytile + 1) * 2 : (K >> 6);

    ld_stage(0, 0);
    ld_stage(1, 64);

    for (int it = 0; it < niter; ++it) {
        int s = it & 1;
        if (it == niter - 1) asm volatile("cp.async.wait_group 0;" ::: "memory");
        else                 asm volatile("cp.async.wait_group 1;" ::: "memory");
        __syncthreads();

        uint32_t ab = base + s * 32768, bb = ab + 16384;
#pragma unroll
        for (int ks = 0; ks < 4; ks++) {
            uint32_t af[4][4], bf[8][2];
#pragma unroll
            for (int t = 0; t < 4; t++) {
                int row = wm * 64 + t * 16 + (lane & 15);
                int ch = ks * 2 + (lane >> 4);
                uint32_t ad = ab + SWZ128((uint32_t)(row * 128 + ch * 16));
                asm volatile(
                    "ldmatrix.sync.aligned.m8n8.x4.shared.b16 {%0,%1,%2,%3}, [%4];"
                    : "=r"(af[t][0]), "=r"(af[t][1]), "=r"(af[t][2]), "=r"(af[t][3])
                    : "r"(ad));
            }
#pragma unroll
            for (int p = 0; p < 4; p++) {
                int nrow = wn * 64 + p * 16 + ((lane >> 4) & 1) * 8 + (lane & 7);
                int ch = ks * 2 + ((lane >> 3) & 1);
                uint32_t bd = bb + SWZ128((uint32_t)(nrow * 128 + ch * 16));
                asm volatile(
                    "ldmatrix.sync.aligned.m8n8.x4.shared.b16 {%0,%1,%2,%3}, [%4];"
                    : "=r"(bf[2*p][0]), "=r"(bf[2*p][1]),
                      "=r"(bf[2*p+1][0]), "=r"(bf[2*p+1][1])
                    : "r"(bd));
            }
#pragma unroll
            for (int t = 0; t < 4; t++)
#pragma unroll
                for (int u = 0; u < 8; u++) {
                    asm volatile(
                        "mma.sync.aligned.m16n8k16.row.col.f32.f16.f16.f32 "
                        "{%0,%1,%2,%3}, {%4,%5,%6,%7}, {%8,%9}, {%0,%1,%2,%3};"
                        : "+f"(acc[t][u][0]), "+f"(acc[t][u][1]),
                          "+f"(acc[t][u][2]), "+f"(acc[t][u][3])
                        : "r"(af[t][0]), "r"(af[t][1]), "r"(af[t][2]), "r"(af[t][3]),
                          "r"(bf[u][0]), "r"(bf[u][1]));
                }
        }
        __syncthreads();
        if (it + 2 < niter) ld_stage(s, (it + 2) << 6);
    }

    const int rb0 = ytile * 128 + wm * 64;
    const int cb0 = blockIdx.x * 128 + wn * 64;
    const int rsub = lane >> 2, csub = (lane & 3) * 2;
#pragma unroll
    for (int t = 0; t < 4; t++) {
        int r0 = rb0 + t * 16 + rsub;
#pragma unroll
        for (int u = 0; u < 8; u++) {
            int col = cb0 + u * 8 + csub;
            float b0 = 0.f, b1 = 0.f;
            if (bias) { b0 = bias[col]; b1 = bias[col + 1]; }
            float v0 = acc[t][u][0] * alpha + b0;
            float v1 = acc[t][u][1] * alpha + b1;
            float v2 = acc[t][u][2] * alpha + b0;
            float v3 = acc[t][u][3] * alpha + b1;
            if (relu) {
                v0 = fmaxf(v0, 0.f); v1 = fmaxf(v1, 0.f);
                v2 = fmaxf(v2, 0.f); v3 = fmaxf(v3, 0.f);
            }
            if (mode == 0) {
                float* Cf = (float*)Cv + blockIdx.z * sC;
                *(float2*)(Cf + (long)r0 * N + col)       = make_float2(v0, v1);
                *(float2*)(Cf + (long)(r0 + 8) * N + col) = make_float2(v2, v3);
            } else if (mode == 1) {
                __half* Ch = (__half*)Cv + blockIdx.z * sC;
                *(__half2*)(Ch + (long)r0 * N + col)       = __floats2half2_rn(v0, v1);
                *(__half2*)(Ch + (long)(r0 + 8) * N + col) = __floats2half2_rn(v2, v3);
            } else if (mode == 2) {
                int h = col >> 7, dk = col & 127;
                __half* Ch = (__half*)Cv;
                {
                    int b = r0 >> 9, ss = r0 & 511;
                    *(__half2*)(Ch + (((long)(b*Hc + h)*Sc + ss)*DKc + dk)) =
                        __floats2half2_rn(v0, v1);
                }
                {
                    int r1 = r0 + 8;
                    int b = r1 >> 9, ss = r1 & 511;
                    *(__half2*)(Ch + (((long)(b*Hc + h)*Sc + ss)*DKc + dk)) =
                        __floats2half2_rn(v2, v3);
                }
            } else {
                int z = blockIdx.z;
                int b = z >> 3, h = z & 7;
                __half* Ch = (__half*)Cv;
                *(__half2*)(Ch + (((long)(b*Sc + r0))*Dc + h*DKc + col)) =
                    __floats2half2_rn(v0, v1);
                *(__half2*)(Ch + (((long)(b*Sc + r0 + 8))*Dc + h*DKc + col)) =
                    __floats2half2_rn(v2, v3);
            }
        }
    }
}

// ---------------- conversions ----------------
__global__ void round_copy3(const float* __restrict__ i0, __half* __restrict__ o0,
                            const float* __restrict__ i1, __half* __restrict__ o1,
                            const float* __restrict__ i2, __half* __restrict__ o2,
                            long n4)
{
    long t = (long)blockIdx.x * blockDim.x + threadIdx.x;
    if (t >= n4) return;
    const float* in; __half* out;
    if (blockIdx.y == 0)      { in = i0; out = o0; }
    else if (blockIdx.y == 1) { in = i1; out = o1; }
    else                      { in = i2; out = o2; }
    float4 v = ((const float4*)in)[t];
    __half2 h0 = __floats2half2_rn(v.x, v.y);
    __half2 h1 = __floats2half2_rn(v.z, v.w);
    *(uint2*)(out + t * 4) = make_uint2(*(uint32_t*)&h0, *(uint32_t*)&h1);
}

__global__ void round_copy2(const float* __restrict__ i0, __half* __restrict__ o0,
                            const float* __restrict__ i1, __half* __restrict__ o1,
                            long n4)
{
    long t = (long)blockIdx.x * blockDim.x + threadIdx.x;
    if (t >= n4) return;
    const float* in = blockIdx.y ? i1 : i0;
    __half* out = blockIdx.y ? o1 : o0;
    float4 v = ((const float4*)in)[t];
    __half2 h0 = __floats2half2_rn(v.x, v.y);
    __half2 h1 = __floats2half2_rn(v.z, v.w);
    *(uint2*)(out + t * 4) = make_uint2(*(uint32_t*)&h0, *(uint32_t*)&h1);
}

__global__ void round_copy_h(const float* __restrict__ in, __half* __restrict__ out, long n4)
{
    long t = (long)blockIdx.x * blockDim.x + threadIdx.x;
    if (t < n4) {
        float4 v = ((const float4*)in)[t];
        __half2 h0 = __floats2half2_rn(v.x, v.y);
        __half2 h1 = __floats2half2_rn(v.z, v.w);
        *(uint2*)(out + t * 4) = make_uint2(*(uint32_t*)&h0, *(uint32_t*)&h1);
    }
}

// (B,S,D) half -> (B,H,DK,S) half
__global__ void to_heads_t_h(const __half* __restrict__ in, __half* __restrict__ out)
{
    int t = blockIdx.x * blockDim.x + threadIdx.x;
    int s = t & (Sc - 1);
    int rest = t >> 9;
    int dq = rest & 31;
    rest >>= 5;
    int h = rest & 7;
    int b = rest >> 3;
    uint2 u = *(const uint2*)(in + ((long)(b*Sc + s) * Dc + h*DKc + dq*4));
    __half2 h0 = *(__half2*)&u.x;
    __half2 h1 = *(__half2*)&u.y;
    long ob = ((long)((b*Hc + h)*DKc) + dq*4) * Sc + s;
    out[ob]        = __low2half(h0);
    out[ob + Sc]   = __high2half(h0);
    out[ob + 2*Sc] = __low2half(h1);
    out[ob + 3*Sc] = __high2half(h1);
}

__global__ void compute_ext(const float* __restrict__ alphas, const float* __restrict__ E,
                            int* __restrict__ ext)
{
    int idx = blockIdx.x * blockDim.x + threadIdx.x;
    if (idx < Hc * Sc) {
        float a0 = alphas[idx*2], a1 = alphas[idx*2+1];
        float g0 = -logf(E[idx*2] + 1e-5f), g1 = -logf(E[idx*2+1] + 1e-5f);
        ext[idx] = ((a0 + g0) < (a1 + g1)) ? 1 : 0;
    }
}

// ---------------- warp-per-row fused softmax pipeline ----------------
__global__ __launch_bounds__(256)
void attn_softmax2(const float* __restrict__ scores, __half* __restrict__ out_h,
                   const int* __restrict__ ext, const float* __restrict__ gam,
                   int bmask, int zero_pad)
{
    const int warp = threadIdx.x >> 5, lane = threadIdx.x & 31;
    const long rid = (long)blockIdx.x * 8 + warp;
    const int i = (int)(rid & (Sc - 1));
    const int h = (int)((rid >> 9) & (Hc - 1));
    const float* row = scores + rid * Sc;
    const int j0 = lane * 16;

    float raw[16];
#pragma unroll
    for (int c = 0; c < 4; c++)
        *(float4*)&raw[c*4] = *(const float4*)(row + j0 + c*4);

    float g = gam[h];
    float sp = (g > 20.f) ? g : log1pf(expf(g));
    const int* exth = ext + h * Sc;

    float m1 = NEGF, v1[16];
#pragma unroll
    for (int c = 0; c < 16; c++) {
        int j = j0 + c;
        int d = j - i; d = d < 0 ? -d : d;
        bool causal = j < i + bmask;
        bool dam = causal || (exth[d] != 0);
        v1[c] = dam ? raw[c] : NEGF;
        m1 = fmaxf(m1, v1[c]);
    }
#pragma unroll
    for (int o = 16; o; o >>= 1) m1 = fmaxf(m1, __shfl_xor_sync(~0u, m1, o));
    float s1 = 0.f, p[16];
#pragma unroll
    for (int c = 0; c < 16; c++) { p[c] = expf(v1[c] - m1); s1 += p[c]; }
#pragma unroll
    for (int o = 16; o; o >>= 1) s1 += __shfl_xor_sync(~0u, s1, o);
    float inv1 = 1.f / s1;

    float run = 0.f, cum[16];
#pragma unroll
    for (int c = 0; c < 16; c++) {
        int j = j0 + c;
        float sc = (j < i + bmask) ? p[c] * inv1 : 0.f;
        run += sc;
        cum[c] = run;
    }
    float excl = run;
#pragma unroll
    for (int o = 1; o < 32; o <<= 1) {
        float t = __shfl_up_sync(~0u, excl, o);
        if (lane >= o) excl += t;
    }
    float tot = __shfl_sync(~0u, excl, 31);
    excl -= run;

    float m2 = NEGF, v2[16];
#pragma unroll
    for (int c = 0; c < 16; c++) {
        int j = j0 + c;
        int d = j - i; d = d < 0 ? -d : d;
        bool causal = j < i + bmask;
        float rem = tot - (excl + cum[c]);
        float dist = sqrtf(fmaxf(rem * (float)d, 0.f));
        float te = expf(dist * (-sp));
        te = fminf(fmaxf(te, 1e-5f), 1e5f);
        v2[c] = causal ? raw[c] * te : NEGF;
        m2 = fmaxf(m2, v2[c]);
    }
#pragma unroll
    for (int o = 16; o; o >>= 1) m2 = fmaxf(m2, __shfl_xor_sync(~0u, m2, o));
    float s2 = 0.f;
#pragma unroll
    for (int c = 0; c < 16; c++) { v2[c] = expf(v2[c] - m2); s2 += v2[c]; }
#pragma unroll
    for (int o = 16; o; o >>= 1) s2 += __shfl_xor_sync(~0u, s2, o);
    float inv2 = 1.f / s2;

    bool zp = (zero_pad && i == 0);
    uint32_t w[8];
#pragma unroll
    for (int c = 0; c < 8; c++) {
        float a = zp ? 0.f : v2[2*c] * inv2;
        float b = zp ? 0.f : v2[2*c+1] * inv2;
        __half2 hh = __floats2half2_rn(a, b);
        w[c] = *(uint32_t*)&hh;
    }
    __half* orow = out_h + rid * Sc + j0;
    *(uint4*)(orow)     = make_uint4(w[0], w[1], w[2], w[3]);
    *(uint4*)(orow + 8) = make_uint4(w[4], w[5], w[6], w[7]);
}

// ---------------- residual + layernorm ----------------
__global__ __launch_bounds__(256)
void add_ln(const float* __restrict__ a, const float* __restrict__ c,
            const float* __restrict__ g, const float* __restrict__ bt,
            float* __restrict__ out, __half* __restrict__ out_h)
{
    const int r = blockIdx.x;
    const long base = (long)r * Dc;
    __shared__ float red[256];
    float vals[4];
    float s = 0.f;
#pragma unroll
    for (int q = 0; q < 4; q++) {
        int ci = threadIdx.x + q * 256;
        vals[q] = a[base + ci] + c[base + ci];
        s += vals[q];
    }
    red[threadIdx.x] = s; __syncthreads();
    for (int off = 128; off; off >>= 1) {
        if (threadIdx.x < off) red[threadIdx.x] += red[threadIdx.x + off];
        __syncthreads();
    }
    float mu = red[0] * (1.f / Dc); __syncthreads();
    float vs = 0.f;
#pragma unroll
    for (int q = 0; q < 4; q++) { float d = vals[q] - mu; vs += d * d; }
    red[threadIdx.x] = vs; __syncthreads();
    for (int off = 128; off; off >>= 1) {
        if (threadIdx.x < off) red[threadIdx.x] += red[threadIdx.x + off];
        __syncthreads();
    }
    float inv = rsqrtf(red[0] * (1.f / Dc) + 1e-5f);
#pragma unroll
    for (int q = 0; q < 4; q++) {
        int ci = threadIdx.x + q * 256;
        float o = (vals[q] - mu) * inv * g[ci] + bt[ci];
        out[base + ci] = o;
        if (out_h) out_h[base + ci] = __float2half_rn(o);
    }
}

// ---------------- host orchestration ----------------
struct LayerBufs {
    __half *qk_h, *v_h, *cat_h, *scores_h;
    float *scores, *proj;
    int* ext;
};
struct Weights {
    __half *wk, *wv, *wo, *w1, *w2;
};

#define GEMM_SMEM 65536

static void vprep(const __half* Vin_h, int l, const float* vb,
                  const Weights& W, const LayerBufs& S, cudaStream_t st)
{
    const long DD = (long)Dc * Dc;
    gemm_h<<<dim3(Dc/128, MROWS/128), 128, GEMM_SMEM, st>>>(
        Vin_h, W.wv + (long)l*DD, vb + (long)l*Dc, S.cat_h, Dc, Dc, 0, 0, 0, 1.f, 0, 1);
    to_heads_t_h<<<(MROWS*Dc/4)/256, 256, 0, st>>>(S.cat_h, S.v_h);
}

static void layer_core(const float* X, const __half* X_h,
                       float* outbuf, __half* outbuf_h,
                       float* t1, __half* t1_h, __half* ff_h,
                       int l, int bmask, int apply_pos,
                       const float* kb, const float* ob,
                       const float* gammas, const float* alphas, const float* gE,
                       const float* ln1g, const float* ln1b,
                       const float* b1, const float* b2,
                       const float* ln2g, const float* ln2b,
                       const Weights& W, const LayerBufs& S,
                       cudaStream_t st, cudaEvent_t evV, cudaEvent_t evFF)
{
    const long DD = (long)Dc * Dc;
    const float scl = 1.0f / sqrtf((float)DKc);
    const long SDK = (long)Sc * DKc;
    const long SS = (long)Sc * Sc;

    float*  ln1o   = apply_pos ? t1   : outbuf;
    __half* ln1o_h = apply_pos ? t1_h : outbuf_h;

    gemm_h<<<dim3(Dc/128, MROWS/128), 128, GEMM_SMEM, st>>>(
        X_h, W.wk + (long)l*DD, kb + (long)l*Dc, S.qk_h, Dc, Dc, 0, 0, 0, 1.f, 0, 2);
    gemm_h<<<dim3(Sc/128, Sc/128, Bc*Hc), 128, GEMM_SMEM, st>>>(
        S.qk_h, S.qk_h, nullptr, S.scores, Sc, DKc, SDK, SDK, SS, scl, 0, 0);
    compute_ext<<<(Hc*Sc + 255)/256, 256, 0, st>>>(alphas + (long)l*Hc*Sc*2,
                                                   gE + (long)l*Hc*Sc*2, S.ext);
    attn_softmax2<<<(Bc*Hc*Sc)/8, 256, 0, st>>>(S.scores, S.scores_h, S.ext,
                                                gammas + (long)l*Hc, bmask, bmask == 0);
    if (evV) cudaStreamWaitEvent(st, evV, 0);
    gemm_h<<<dim3(1, Sc/128, Bc*Hc), 128, GEMM_SMEM, st>>>(
        S.scores_h, S.v_h, nullptr, S.cat_h, DKc, Sc, SS, SDK, 0, 1.f, 0, 3);
    gemm_h<<<dim3(Dc/128, MROWS/128), 128, GEMM_SMEM, st>>>(
        S.cat_h, W.wo + (long)l*DD, ob + (long)l*Dc, S.proj, Dc, Dc, 0, 0, 0, 1.f, 0, 0);
    add_ln<<<MROWS, 256, 0, st>>>(X, S.proj, ln1g + (long)l*Dc, ln1b + (long)l*Dc,
                                  ln1o, ln1o_h);

    if (apply_pos) {
        if (evFF) cudaStreamWaitEvent(st, evFF, 0);
        gemm_h<<<dim3(DFFc/128, MROWS/128), 128, GEMM_SMEM, st>>>(
            t1_h, W.w1 + (long)l*DFFc*Dc, b1 + (long)l*DFFc, ff_h,
            DFFc, Dc, 0, 0, 0, 1.f, 1, 1);
        gemm_h<<<dim3(Dc/128, MROWS/128), 128, GEMM_SMEM, st>>>(
            ff_h, W.w2 + (long)l*Dc*DFFc, b2 + (long)l*Dc, S.proj,
            Dc, DFFc, 0, 0, 0, 1.f, 0, 0);
        add_ln<<<MROWS, 256, 0, st>>>(t1, S.proj, ln2g + (long)l*Dc, ln2b + (long)l*Dc,
                                      outbuf, outbuf_h);
    }
}

extern "C" void kernel_launch(void* const* d_in, const int* in_sizes, int n_in,
                              void* d_out, int out_size)
{
    const float* q_embed  = (const float*)d_in[0];
    const float* qa_embed = (const float*)d_in[1];
    const float* kW = (const float*)d_in[2];
    const float* kb = (const float*)d_in[3];
    const float* vW = (const float*)d_in[4];
    const float* vb = (const float*)d_in[5];
    const float* oW = (const float*)d_in[6];
    const float* ob = (const float*)d_in[7];
    const float* gammas = (const float*)d_in[8];
    const float* alphas = (const float*)d_in[9];
    const float* ln1g = (const float*)d_in[10];
    const float* ln1b = (const float*)d_in[11];
    const float* w1 = (const float*)d_in[12];
    const float* b1 = (const float*)d_in[13];
    const float* w2 = (const float*)d_in[14];
    const float* b2 = (const float*)d_in[15];
    const float* ln2g = (const float*)d_in[16];
    const float* ln2b = (const float*)d_in[17];
    const float* gE = (const float*)d_in[18];
    float* out = (float*)d_out;

    Weights W;
    cudaGetSymbolAddress((void**)&W.wk, g_wk_h);
    cudaGetSymbolAddress((void**)&W.wv, g_wv_h);
    cudaGetSymbolAddress((void**)&W.wo, g_wo_h);
    cudaGetSymbolAddress((void**)&W.w1, g_w1_h);
    cudaGetSymbolAddress((void**)&W.w2, g_w2_h);

    LayerBufs A, B2;
    cudaGetSymbolAddress((void**)&A.qk_h, g_qk_h);
    cudaGetSymbolAddress((void**)&A.v_h, g_v_h);
    cudaGetSymbolAddress((void**)&A.cat_h, g_cat_h);
    cudaGetSymbolAddress((void**)&A.scores, g_scores);
    cudaGetSymbolAddress((void**)&A.scores_h, g_scores_h);
    cudaGetSymbolAddress((void**)&A.proj, g_proj);
    cudaGetSymbolAddress((void**)&A.ext, g_ext);
    cudaGetSymbolAddress((void**)&B2.qk_h, g_qk2_h);
    cudaGetSymbolAddress((void**)&B2.v_h, g_v2_h);
    cudaGetSymbolAddress((void**)&B2.cat_h, g_cat2_h);
    cudaGetSymbolAddress((void**)&B2.scores, g_scores2);
    cudaGetSymbolAddress((void**)&B2.scores_h, g_scores2_h);
    cudaGetSymbolAddress((void**)&B2.proj, g_proj2);
    cudaGetSymbolAddress((void**)&B2.ext, g_ext2);

    __half *qa_h, *q_h, *y_h, *xb_h, *t1_h, *ff_h;
    float *y, *xb, *t1;
    cudaGetSymbolAddress((void**)&qa_h, g_qa_h);
    cudaGetSymbolAddress((void**)&q_h, g_q_h);
    cudaGetSymbolAddress((void**)&y, g_y);
    cudaGetSymbolAddress((void**)&y_h, g_y_h);
    cudaGetSymbolAddress((void**)&xb, g_xb);
    cudaGetSymbolAddress((void**)&xb_h, g_xb_h);
    cudaGetSymbolAddress((void**)&t1, g_t1);
    cudaGetSymbolAddress((void**)&t1_h, g_t1_h);
    cudaGetSymbolAddress((void**)&ff_h, g_ff_h);

    cudaFuncSetAttribute(gemm_h, cudaFuncAttributeMaxDynamicSharedMemorySize, GEMM_SMEM);

    cudaStream_t s2;
    cudaStreamCreateWithFlags(&s2, cudaStreamNonBlocking);
    cudaEvent_t eFork, eW, eQA, eFF, eV0, eL1, eY, eV2, eJoin;
    cudaEventCreateWithFlags(&eFork, cudaEventDisableTiming);
    cudaEventCreateWithFlags(&eW, cudaEventDisableTiming);
    cudaEventCreateWithFlags(&eQA, cudaEventDisableTiming);
    cudaEventCreateWithFlags(&eFF, cudaEventDisableTiming);
    cudaEventCreateWithFlags(&eV0, cudaEventDisableTiming);
    cudaEventCreateWithFlags(&eL1, cudaEventDisableTiming);
    cudaEventCreateWithFlags(&eY, cudaEventDisableTiming);
    cudaEventCreateWithFlags(&eV2, cudaEventDisableTiming);
    cudaEventCreateWithFlags(&eJoin, cudaEventDisableTiming);

    long nDD4 = (long)3 * Dc * Dc / 4;
    long nFF4 = (long)3 * DFFc * Dc / 4;
    long nX4  = (long)MROWS * Dc / 4;

    cudaEventRecord(eFork, 0);
    cudaStreamWaitEvent(s2, eFork, 0);

    round_copy3<<<dim3((unsigned)((nDD4 + 255) / 256), 3), 256>>>(
        kW, W.wk, vW, W.wv, oW, W.wo, nDD4);
    cudaEventRecord(eW, 0);
    round_copy_h<<<(int)((nX4 + 255) / 256), 256>>>(qa_embed, qa_h, nX4);
    cudaEventRecord(eQA, 0);

    round_copy2<<<dim3((unsigned)((nFF4 + 255) / 256), 2), 256, 0, s2>>>(
        w1, W.w1, w2, W.w2, nFF4);
    cudaEventRecord(eFF, s2);
    round_copy_h<<<(int)((nX4 + 255) / 256), 256, 0, s2>>>(q_embed, q_h, nX4);
    cudaStreamWaitEvent(s2, eW, 0);
    cudaStreamWaitEvent(s2, eQA, 0);
    vprep(qa_h, 0, vb, W, A, s2);
    cudaEventRecord(eV0, s2);

    layer_core(qa_embed, qa_h, y, y_h, t1, t1_h, ff_h, 0, 1, 1,
               kb, ob, gammas, alphas, gE, ln1g, ln1b, b1, b2, ln2g, ln2b,
               W, A, 0, eV0, eFF);
    cudaEventRecord(eY, 0);

    vprep(q_h, 1, vb, W, B2, s2);
    layer_core(q_embed, q_h, xb, xb_h, nullptr, nullptr, nullptr, 1, 1, 0,
               kb, ob, gammas, alphas, gE, ln1g, ln1b, b1, b2, ln2g, ln2b,
               W, B2, s2, nullptr, nullptr);
    cudaEventRecord(eL1, s2);

    cudaStreamWaitEvent(s2, eY, 0);
    vprep(y_h, 2, vb, W, A, s2);
    cudaEventRecord(eV2, s2);

    cudaStreamWaitEvent(0, eL1, 0);
    layer_core(xb, xb_h, out, nullptr, t1, t1_h, ff_h, 2, 0, 1,
               kb, ob, gammas, alphas, gE, ln1g, ln1b, b1, b2, ln2g, ln2b,
               W, A, 0, eV2, nullptr);

    cudaEventRecord(eJoin, s2);
    cudaStreamWaitEvent(0, eJoin, 0);
}

// round 17
// speedup vs baseline: 1.0292x; 1.0073x over previous
#include <cuda_runtime.h>
#include <cuda_fp16.h>
#include <math.h>
#include <stdint.h>

#define Bc 16
#define Sc 512
#define Dc 1024
#define Hc 8
#define DFFc 4096
#define DKc 128
#define MROWS (Bc*Sc)
#define NEGF (-1e32f)

// ---------------- scratch ----------------
__device__ __half g_wk_h[(size_t)3*Dc*Dc];
__device__ __half g_wv_h[(size_t)3*Dc*Dc];
__device__ __half g_wo_h[(size_t)3*Dc*Dc];
__device__ __half g_w1_h[(size_t)3*DFFc*Dc];
__device__ __half g_w2_h[(size_t)3*Dc*DFFc];
__device__ __half g_qa_h[(size_t)MROWS*Dc];
__device__ __half g_q_h[(size_t)MROWS*Dc];
__device__ float  g_y[(size_t)MROWS*Dc];
__device__ __half g_y_h[(size_t)MROWS*Dc];
__device__ float  g_xb[(size_t)MROWS*Dc];
__device__ __half g_xb_h[(size_t)MROWS*Dc];
__device__ float  g_t1[(size_t)MROWS*Dc];
__device__ __half g_t1_h[(size_t)MROWS*Dc];
// buffer set A (layers 0,2-V)
__device__ __half g_cat_h[(size_t)MROWS*Dc];
__device__ float  g_proj[(size_t)MROWS*Dc];
__device__ __half g_qk_h[(size_t)MROWS*Dc];
__device__ __half g_v_h[(size_t)MROWS*Dc];
__device__ float  g_scores[(size_t)Bc*Hc*Sc*Sc];
__device__ __half g_scores_h[(size_t)Bc*Hc*Sc*Sc];
__device__ int    g_ext[Hc*Sc];
// buffer set B (layer 1 + layer 2 q-chain)
__device__ __half g_cat2_h[(size_t)MROWS*Dc];
__device__ float  g_proj2[(size_t)MROWS*Dc];
__device__ __half g_qk2_h[(size_t)MROWS*Dc];
__device__ __half g_v2_h[(size_t)MROWS*Dc];
__device__ float  g_scores2[(size_t)Bc*Hc*Sc*Sc];
__device__ __half g_scores2_h[(size_t)Bc*Hc*Sc*Sc];
__device__ int    g_ext2[Hc*Sc];
__device__ __half g_ff_h[(size_t)MROWS*DFFc];

__device__ __forceinline__ void cp16(uint32_t dst, const void* src) {
    asm volatile("cp.async.cg.shared.global [%0], [%1], 16;" :: "r"(dst), "l"(src));
}
#define SWZ128(x) ((x) ^ (((x) >> 3) & 0x70))

// ---- fp16 tensor GEMM: C = alpha*A(M,K)@B(N,K)^T + bias.
// CTA tile 128x128, BK=64, 128 threads (4 warps 2x2, 64x64), 2-stage cp.async.
// mode: 0=float flat, 1=half flat, 2=half [B,H,S,DK] heads,
//       3=half (B,S,D) att concat + causal K-limit (heavy tiles first)
__global__ __launch_bounds__(128, 2)
void gemm_h(const __half* __restrict__ A, const __half* __restrict__ Bm,
            const float* __restrict__ bias, void* __restrict__ Cv,
            int N, int K, long sA, long sB, long sC,
            float alpha, int relu, int mode)
{
    extern __shared__ __half sm[];
    const int tid = threadIdx.x, warp = tid >> 5, lane = tid & 31;
    const int wm = warp >> 1, wn = warp & 1;

    const int ytile = (mode == 3) ? (int)(gridDim.y - 1 - blockIdx.y) : (int)blockIdx.y;

    const __half* Ab = A + blockIdx.z * sA + (long)ytile * 128 * K;
    const __half* Bb = Bm + blockIdx.z * sB + (long)blockIdx.x * 128 * K;

    float acc[4][8][4];
#pragma unroll
    for (int t = 0; t < 4; t++)
#pragma unroll
        for (int u = 0; u < 8; u++)
#pragma unroll
            for (int r = 0; r < 4; r++) acc[t][u][r] = 0.f;

    const uint32_t base = (uint32_t)__cvta_generic_to_shared(sm);
    auto ld_stage = [&](int s, int k0) {
        uint32_t ab = base + s * 32768, bb = ab + 16384;
#pragma unroll
        for (int q = 0; q < 8; q++) {
            int idx = q * 128 + tid;
            int row = idx >> 3, c = idx & 7;
            uint32_t off = SWZ128((uint32_t)(row * 128 + c * 16));
            long gofs = (long)row * K + k0 + c * 8;
            cp16(ab + off, Ab + gofs);
            cp16(bb + off, Bb + gofs);
        }
        asm volatile("cp.async.commit_group;" ::: "memory");
    };

    const int niter = (mode == 3) ? (ytile + 1) * 2 : (K >> 6);

    ld_stage(0, 0);
    ld_stage(1, 64);

    for (int it = 0; it < niter; ++it) {
        int s = it & 1;
        if (it == niter - 1) asm volatile("cp.async.wait_group 0;" ::: "memory");
        else                 asm volatile("cp.async.wait_group 1;" ::: "memory");
        __syncthreads();

        uint32_t ab = base + s * 32768, bb = ab + 16384;
#pragma unroll
        for (int ks = 0; ks < 4; ks++) {
            uint32_t af[4][4], bf[8][2];
#pragma unroll
            for (int t = 0; t < 4; t++) {
                int row = wm * 64 + t * 16 + (lane & 15);
                int ch = ks * 2 + (lane >> 4);
                uint32_t ad = ab + SWZ128((uint32_t)(row * 128 + ch * 16));
                asm volatile(
                    "ldmatrix.sync.aligned.m8n8.x4.shared.b16 {%0,%1,%2,%3}, [%4];"
                    : "=r"(af[t][0]), "=r"(af[t][1]), "=r"(af[t][2]), "=r"(af[t][3])
                    : "r"(ad));
            }
#pragma unroll
            for (int p = 0; p < 4; p++) {
                int nrow = wn * 64 + p * 16 + ((lane >> 4) & 1) * 8 + (lane & 7);
                int ch = ks * 2 + ((lane >> 3) & 1);
                uint32_t bd = bb + SWZ128((uint32_t)(nrow * 128 + ch * 16));
                asm volatile(
                    "ldmatrix.sync.aligned.m8n8.x4.shared.b16 {%0,%1,%2,%3}, [%4];"
                    : "=r"(bf[2*p][0]), "=r"(bf[2*p][1]),
                      "=r"(bf[2*p+1][0]), "=r"(bf[2*p+1][1])
                    : "r"(bd));
            }
#pragma unroll
            for (int t = 0; t < 4; t++)
#pragma unroll
                for (int u = 0; u < 8; u++) {
                    asm volatile(
                        "mma.sync.aligned.m16n8k16.row.col.f32.f16.f16.f32 "
                        "{%0,%1,%2,%3}, {%4,%5,%6,%7}, {%8,%9}, {%0,%1,%2,%3};"
                        : "+f"(acc[t][u][0]), "+f"(acc[t][u][1]),
                          "+f"(acc[t][u][2]), "+f"(acc[t][u][3])
                        : "r"(af[t][0]), "r"(af[t][1]), "r"(af[t][2]), "r"(af[t][3]),
                          "r"(bf[u][0]), "r"(bf[u][1]));
                }
        }
        __syncthreads();
        if (it + 2 < niter) ld_stage(s, (it + 2) << 6);
    }

    const int rb0 = ytile * 128 + wm * 64;
    const int cb0 = blockIdx.x * 128 + wn * 64;
    const int rsub = lane >> 2, csub = (lane & 3) * 2;
#pragma unroll
    for (int t = 0; t < 4; t++) {
        int r0 = rb0 + t * 16 + rsub;
#pragma unroll
        for (int u = 0; u < 8; u++) {
            int col = cb0 + u * 8 + csub;
            float b0 = 0.f, b1 = 0.f;
            if (bias) { b0 = bias[col]; b1 = bias[col + 1]; }
            float v0 = acc[t][u][0] * alpha + b0;
            float v1 = acc[t][u][1] * alpha + b1;
            float v2 = acc[t][u][2] * alpha + b0;
            float v3 = acc[t][u][3] * alpha + b1;
            if (relu) {
                v0 = fmaxf(v0, 0.f); v1 = fmaxf(v1, 0.f);
                v2 = fmaxf(v2, 0.f); v3 = fmaxf(v3, 0.f);
            }
            if (mode == 0) {
                float* Cf = (float*)Cv + blockIdx.z * sC;
                *(float2*)(Cf + (long)r0 * N + col)       = make_float2(v0, v1);
                *(float2*)(Cf + (long)(r0 + 8) * N + col) = make_float2(v2, v3);
            } else if (mode == 1) {
                __half* Ch = (__half*)Cv + blockIdx.z * sC;
                *(__half2*)(Ch + (long)r0 * N + col)       = __floats2half2_rn(v0, v1);
                *(__half2*)(Ch + (long)(r0 + 8) * N + col) = __floats2half2_rn(v2, v3);
            } else if (mode == 2) {
                int h = col >> 7, dk = col & 127;
                __half* Ch = (__half*)Cv;
                {
                    int b = r0 >> 9, ss = r0 & 511;
                    *(__half2*)(Ch + (((long)(b*Hc + h)*Sc + ss)*DKc + dk)) =
                        __floats2half2_rn(v0, v1);
                }
                {
                    int r1 = r0 + 8;
                    int b = r1 >> 9, ss = r1 & 511;
                    *(__half2*)(Ch + (((long)(b*Hc + h)*Sc + ss)*DKc + dk)) =
                        __floats2half2_rn(v2, v3);
                }
            } else {
                int z = blockIdx.z;
                int b = z >> 3, h = z & 7;
                __half* Ch = (__half*)Cv;
                *(__half2*)(Ch + (((long)(b*Sc + r0))*Dc + h*DKc + col)) =
                    __floats2half2_rn(v0, v1);
                *(__half2*)(Ch + (((long)(b*Sc + r0 + 8))*Dc + h*DKc + col)) =
                    __floats2half2_rn(v2, v3);
            }
        }
    }
}

// ---------------- conversions ----------------
__global__ void round_copy3(const float* __restrict__ i0, __half* __restrict__ o0,
                            const float* __restrict__ i1, __half* __restrict__ o1,
                            const float* __restrict__ i2, __half* __restrict__ o2,
                            long n4)
{
    long t = (long)blockIdx.x * blockDim.x + threadIdx.x;
    if (t >= n4) return;
    const float* in; __half* out;
    if (blockIdx.y == 0)      { in = i0; out = o0; }
    else if (blockIdx.y == 1) { in = i1; out = o1; }
    else                      { in = i2; out = o2; }
    float4 v = ((const float4*)in)[t];
    __half2 h0 = __floats2half2_rn(v.x, v.y);
    __half2 h1 = __floats2half2_rn(v.z, v.w);
    *(uint2*)(out + t * 4) = make_uint2(*(uint32_t*)&h0, *(uint32_t*)&h1);
}

__global__ void round_copy2(const float* __restrict__ i0, __half* __restrict__ o0,
                            const float* __restrict__ i1, __half* __restrict__ o1,
                            long n4)
{
    long t = (long)blockIdx.x * blockDim.x + threadIdx.x;
    if (t >= n4) return;
    const float* in = blockIdx.y ? i1 : i0;
    __half* out = blockIdx.y ? o1 : o0;
    float4 v = ((const float4*)in)[t];
    __half2 h0 = __floats2half2_rn(v.x, v.y);
    __half2 h1 = __floats2half2_rn(v.z, v.w);
    *(uint2*)(out + t * 4) = make_uint2(*(uint32_t*)&h0, *(uint32_t*)&h1);
}

__global__ void round_copy_h(const float* __restrict__ in, __half* __restrict__ out, long n4)
{
    long t = (long)blockIdx.x * blockDim.x + threadIdx.x;
    if (t < n4) {
        float4 v = ((const float4*)in)[t];
        __half2 h0 = __floats2half2_rn(v.x, v.y);
        __half2 h1 = __floats2half2_rn(v.z, v.w);
        *(uint2*)(out + t * 4) = make_uint2(*(uint32_t*)&h0, *(uint32_t*)&h1);
    }
}

// (B,S,D) half -> (B,H,DK,S) half
__global__ void to_heads_t_h(const __half* __restrict__ in, __half* __restrict__ out)
{
    int t = blockIdx.x * blockDim.x + threadIdx.x;
    int s = t & (Sc - 1);
    int rest = t >> 9;
    int dq = rest & 31;
    rest >>= 5;
    int h = rest & 7;
    int b = rest >> 3;
    uint2 u = *(const uint2*)(in + ((long)(b*Sc + s) * Dc + h*DKc + dq*4));
    __half2 h0 = *(__half2*)&u.x;
    __half2 h1 = *(__half2*)&u.y;
    long ob = ((long)((b*Hc + h)*DKc) + dq*4) * Sc + s;
    out[ob]        = __low2half(h0);
    out[ob + Sc]   = __high2half(h0);
    out[ob + 2*Sc] = __low2half(h1);
    out[ob + 3*Sc] = __high2half(h1);
}

__global__ void compute_ext(const float* __restrict__ alphas, const float* __restrict__ E,
                            int* __restrict__ ext)
{
    int idx = blockIdx.x * blockDim.x + threadIdx.x;
    if (idx < Hc * Sc) {
        float a0 = alphas[idx*2], a1 = alphas[idx*2+1];
        float g0 = -logf(E[idx*2] + 1e-5f), g1 = -logf(E[idx*2+1] + 1e-5f);
        ext[idx] = ((a0 + g0) < (a1 + g1)) ? 1 : 0;
    }
}

// ---------------- warp-per-row fused softmax pipeline ----------------
__global__ __launch_bounds__(256)
void attn_softmax2(const float* __restrict__ scores, __half* __restrict__ out_h,
                   const int* __restrict__ ext, const float* __restrict__ gam,
                   int bmask, int zero_pad)
{
    const int warp = threadIdx.x >> 5, lane = threadIdx.x & 31;
    const long rid = (long)blockIdx.x * 8 + warp;
    const int i = (int)(rid & (Sc - 1));
    const int h = (int)((rid >> 9) & (Hc - 1));
    const float* row = scores + rid * Sc;
    const int j0 = lane * 16;

    float raw[16];
#pragma unroll
    for (int c = 0; c < 4; c++)
        *(float4*)&raw[c*4] = *(const float4*)(row + j0 + c*4);

    float g = gam[h];
    float sp = (g > 20.f) ? g : log1pf(expf(g));
    const int* exth = ext + h * Sc;

    float m1 = NEGF, v1[16];
#pragma unroll
    for (int c = 0; c < 16; c++) {
        int j = j0 + c;
        int d = j - i; d = d < 0 ? -d : d;
        bool causal = j < i + bmask;
        bool dam = causal || (exth[d] != 0);
        v1[c] = dam ? raw[c] : NEGF;
        m1 = fmaxf(m1, v1[c]);
    }
#pragma unroll
    for (int o = 16; o; o >>= 1) m1 = fmaxf(m1, __shfl_xor_sync(~0u, m1, o));
    float s1 = 0.f, p[16];
#pragma unroll
    for (int c = 0; c < 16; c++) { p[c] = expf(v1[c] - m1); s1 += p[c]; }
#pragma unroll
    for (int o = 16; o; o >>= 1) s1 += __shfl_xor_sync(~0u, s1, o);
    float inv1 = 1.f / s1;

    float run = 0.f, cum[16];
#pragma unroll
    for (int c = 0; c < 16; c++) {
        int j = j0 + c;
        float sc = (j < i + bmask) ? p[c] * inv1 : 0.f;
        run += sc;
        cum[c] = run;
    }
    float excl = run;
#pragma unroll
    for (int o = 1; o < 32; o <<= 1) {
        float t = __shfl_up_sync(~0u, excl, o);
        if (lane >= o) excl += t;
    }
    float tot = __shfl_sync(~0u, excl, 31);
    excl -= run;

    float m2 = NEGF, v2[16];
#pragma unroll
    for (int c = 0; c < 16; c++) {
        int j = j0 + c;
        int d = j - i; d = d < 0 ? -d : d;
        bool causal = j < i + bmask;
        float rem = tot - (excl + cum[c]);
        float dist = sqrtf(fmaxf(rem * (float)d, 0.f));
        float te = expf(dist * (-sp));
        te = fminf(fmaxf(te, 1e-5f), 1e5f);
        v2[c] = causal ? raw[c] * te : NEGF;
        m2 = fmaxf(m2, v2[c]);
    }
#pragma unroll
    for (int o = 16; o; o >>= 1) m2 = fmaxf(m2, __shfl_xor_sync(~0u, m2, o));
    float s2 = 0.f;
#pragma unroll
    for (int c = 0; c < 16; c++) { v2[c] = expf(v2[c] - m2); s2 += v2[c]; }
#pragma unroll
    for (int o = 16; o; o >>= 1) s2 += __shfl_xor_sync(~0u, s2, o);
    float inv2 = 1.f / s2;

    bool zp = (zero_pad && i == 0);
    uint32_t w[8];
#pragma unroll
    for (int c = 0; c < 8; c++) {
        float a = zp ? 0.f : v2[2*c] * inv2;
        float b = zp ? 0.f : v2[2*c+1] * inv2;
        __half2 hh = __floats2half2_rn(a, b);
        w[c] = *(uint32_t*)&hh;
    }
    __half* orow = out_h + rid * Sc + j0;
    *(uint4*)(orow)     = make_uint4(w[0], w[1], w[2], w[3]);
    *(uint4*)(orow + 8) = make_uint4(w[4], w[5], w[6], w[7]);
}

// ---------------- residual + layernorm ----------------
__global__ __launch_bounds__(256)
void add_ln(const float* __restrict__ a, const float* __restrict__ c,
            const float* __restrict__ g, const float* __restrict__ bt,
            float* __restrict__ out, __half* __restrict__ out_h)
{
    const int r = blockIdx.x;
    const long base = (long)r * Dc;
    __shared__ float red[256];
    float vals[4];
    float s = 0.f;
#pragma unroll
    for (int q = 0; q < 4; q++) {
        int ci = threadIdx.x + q * 256;
        vals[q] = a[base + ci] + c[base + ci];
        s += vals[q];
    }
    red[threadIdx.x] = s; __syncthreads();
    for (int off = 128; off; off >>= 1) {
        if (threadIdx.x < off) red[threadIdx.x] += red[threadIdx.x + off];
        __syncthreads();
    }
    float mu = red[0] * (1.f / Dc); __syncthreads();
    float vs = 0.f;
#pragma unroll
    for (int q = 0; q < 4; q++) { float d = vals[q] - mu; vs += d * d; }
    red[threadIdx.x] = vs; __syncthreads();
    for (int off = 128; off; off >>= 1) {
        if (threadIdx.x < off) red[threadIdx.x] += red[threadIdx.x + off];
        __syncthreads();
    }
    float inv = rsqrtf(red[0] * (1.f / Dc) + 1e-5f);
#pragma unroll
    for (int q = 0; q < 4; q++) {
        int ci = threadIdx.x + q * 256;
        float o = (vals[q] - mu) * inv * g[ci] + bt[ci];
        out[base + ci] = o;
        if (out_h) out_h[base + ci] = __float2half_rn(o);
    }
}

// ---------------- host orchestration ----------------
struct LayerBufs {
    __half *qk_h, *v_h, *cat_h, *scores_h;
    float *scores, *proj;
    int* ext;
};
struct Weights {
    __half *wk, *wv, *wo, *w1, *w2;
};

#define GEMM_SMEM 65536

static void vprep(const __half* Vin_h, int l, const float* vb,
                  const Weights& W, const LayerBufs& S, cudaStream_t st)
{
    const long DD = (long)Dc * Dc;
    gemm_h<<<dim3(Dc/128, MROWS/128), 128, GEMM_SMEM, st>>>(
        Vin_h, W.wv + (long)l*DD, vb + (long)l*Dc, S.cat_h, Dc, Dc, 0, 0, 0, 1.f, 0, 1);
    to_heads_t_h<<<(MROWS*Dc/4)/256, 256, 0, st>>>(S.cat_h, S.v_h);
}

// q-projection -> scores -> ext -> softmax (writes S.qk_h, S.scores, S.scores_h, S.ext)
static void qchain(const __half* X_h, int l, int bmask,
                   const float* kb, const float* gammas, const float* alphas,
                   const float* gE, const Weights& W, const LayerBufs& S,
                   cudaStream_t st)
{
    const long DD = (long)Dc * Dc;
    const float scl = 1.0f / sqrtf((float)DKc);
    const long SDK = (long)Sc * DKc;
    const long SS = (long)Sc * Sc;
    gemm_h<<<dim3(Dc/128, MROWS/128), 128, GEMM_SMEM, st>>>(
        X_h, W.wk + (long)l*DD, kb + (long)l*Dc, S.qk_h, Dc, Dc, 0, 0, 0, 1.f, 0, 2);
    gemm_h<<<dim3(Sc/128, Sc/128, Bc*Hc), 128, GEMM_SMEM, st>>>(
        S.qk_h, S.qk_h, nullptr, S.scores, Sc, DKc, SDK, SDK, SS, scl, 0, 0);
    compute_ext<<<(Hc*Sc + 255)/256, 256, 0, st>>>(alphas + (long)l*Hc*Sc*2,
                                                   gE + (long)l*Hc*Sc*2, S.ext);
    attn_softmax2<<<(Bc*Hc*Sc)/8, 256, 0, st>>>(S.scores, S.scores_h, S.ext,
                                                gammas + (long)l*Hc, bmask, bmask == 0);
}

// att@V -> o-proj -> LN (+FFN). v_h read from vS; probs from qS.
static void tail(const float* X, float* outbuf, __half* outbuf_h,
                 float* t1, __half* t1_h, __half* ff_h,
                 int l, int apply_pos,
                 const float* ob, const float* ln1g, const float* ln1b,
                 const float* b1, const float* b2,
                 const float* ln2g, const float* ln2b,
                 const Weights& W, const LayerBufs& qS, const LayerBufs& vS,
                 cudaStream_t st)
{
    const long DD = (long)Dc * Dc;
    const long SDK = (long)Sc * DKc;
    const long SS = (long)Sc * Sc;

    float*  ln1o   = apply_pos ? t1   : outbuf;
    __half* ln1o_h = apply_pos ? t1_h : outbuf_h;

    gemm_h<<<dim3(1, Sc/128, Bc*Hc), 128, GEMM_SMEM, st>>>(
        qS.scores_h, vS.v_h, nullptr, qS.cat_h, DKc, Sc, SS, SDK, 0, 1.f, 0, 3);
    gemm_h<<<dim3(Dc/128, MROWS/128), 128, GEMM_SMEM, st>>>(
        qS.cat_h, W.wo + (long)l*DD, ob + (long)l*Dc, qS.proj, Dc, Dc, 0, 0, 0, 1.f, 0, 0);
    add_ln<<<MROWS, 256, 0, st>>>(X, qS.proj, ln1g + (long)l*Dc, ln1b + (long)l*Dc,
                                  ln1o, ln1o_h);
    if (apply_pos) {
        gemm_h<<<dim3(DFFc/128, MROWS/128), 128, GEMM_SMEM, st>>>(
            t1_h, W.w1 + (long)l*DFFc*Dc, b1 + (long)l*DFFc, ff_h,
            DFFc, Dc, 0, 0, 0, 1.f, 1, 1);
        gemm_h<<<dim3(Dc/128, MROWS/128), 128, GEMM_SMEM, st>>>(
            ff_h, W.w2 + (long)l*Dc*DFFc, b2 + (long)l*Dc, qS.proj,
            Dc, DFFc, 0, 0, 0, 1.f, 0, 0);
        add_ln<<<MROWS, 256, 0, st>>>(t1, qS.proj, ln2g + (long)l*Dc, ln2b + (long)l*Dc,
                                      outbuf, outbuf_h);
    }
}

extern "C" void kernel_launch(void* const* d_in, const int* in_sizes, int n_in,
                              void* d_out, int out_size)
{
    const float* q_embed  = (const float*)d_in[0];
    const float* qa_embed = (const float*)d_in[1];
    const float* kW = (const float*)d_in[2];
    const float* kb = (const float*)d_in[3];
    const float* vW = (const float*)d_in[4];
    const float* vb = (const float*)d_in[5];
    const float* oW = (const float*)d_in[6];
    const float* ob = (const float*)d_in[7];
    const float* gammas = (const float*)d_in[8];
    const float* alphas = (const float*)d_in[9];
    const float* ln1g = (const float*)d_in[10];
    const float* ln1b = (const float*)d_in[11];
    const float* w1 = (const float*)d_in[12];
    const float* b1 = (const float*)d_in[13];
    const float* w2 = (const float*)d_in[14];
    const float* b2 = (const float*)d_in[15];
    const float* ln2g = (const float*)d_in[16];
    const float* ln2b = (const float*)d_in[17];
    const float* gE = (const float*)d_in[18];
    float* out = (float*)d_out;

    Weights W;
    cudaGetSymbolAddress((void**)&W.wk, g_wk_h);
    cudaGetSymbolAddress((void**)&W.wv, g_wv_h);
    cudaGetSymbolAddress((void**)&W.wo, g_wo_h);
    cudaGetSymbolAddress((void**)&W.w1, g_w1_h);
    cudaGetSymbolAddress((void**)&W.w2, g_w2_h);

    LayerBufs A, B2;
    cudaGetSymbolAddress((void**)&A.qk_h, g_qk_h);
    cudaGetSymbolAddress((void**)&A.v_h, g_v_h);
    cudaGetSymbolAddress((void**)&A.cat_h, g_cat_h);
    cudaGetSymbolAddress((void**)&A.scores, g_scores);
    cudaGetSymbolAddress((void**)&A.scores_h, g_scores_h);
    cudaGetSymbolAddress((void**)&A.proj, g_proj);
    cudaGetSymbolAddress((void**)&A.ext, g_ext);
    cudaGetSymbolAddress((void**)&B2.qk_h, g_qk2_h);
    cudaGetSymbolAddress((void**)&B2.v_h, g_v2_h);
    cudaGetSymbolAddress((void**)&B2.cat_h, g_cat2_h);
    cudaGetSymbolAddress((void**)&B2.scores, g_scores2);
    cudaGetSymbolAddress((void**)&B2.scores_h, g_scores2_h);
    cudaGetSymbolAddress((void**)&B2.proj, g_proj2);
    cudaGetSymbolAddress((void**)&B2.ext, g_ext2);

    __half *qa_h, *q_h, *y_h, *xb_h, *t1_h, *ff_h;
    float *y, *xb, *t1;
    cudaGetSymbolAddress((void**)&qa_h, g_qa_h);
    cudaGetSymbolAddress((void**)&q_h, g_q_h);
    cudaGetSymbolAddress((void**)&y, g_y);
    cudaGetSymbolAddress((void**)&y_h, g_y_h);
    cudaGetSymbolAddress((void**)&xb, g_xb);
    cudaGetSymbolAddress((void**)&xb_h, g_xb_h);
    cudaGetSymbolAddress((void**)&t1, g_t1);
    cudaGetSymbolAddress((void**)&t1_h, g_t1_h);
    cudaGetSymbolAddress((void**)&ff_h, g_ff_h);

    cudaFuncSetAttribute(gemm_h, cudaFuncAttributeMaxDynamicSharedMemorySize, GEMM_SMEM);

    cudaStream_t s2;
    cudaStreamCreateWithFlags(&s2, cudaStreamNonBlocking);
    cudaEvent_t eFork, eW, eQA, eFF, eV0, eY, eS2, eV2, eJoin;
    cudaEventCreateWithFlags(&eFork, cudaEventDisableTiming);
    cudaEventCreateWithFlags(&eW, cudaEventDisableTiming);
    cudaEventCreateWithFlags(&eQA, cudaEventDisableTiming);
    cudaEventCreateWithFlags(&eFF, cudaEventDisableTiming);
    cudaEventCreateWithFlags(&eV0, cudaEventDisableTiming);
    cudaEventCreateWithFlags(&eY, cudaEventDisableTiming);
    cudaEventCreateWithFlags(&eS2, cudaEventDisableTiming);
    cudaEventCreateWithFlags(&eV2, cudaEventDisableTiming);
    cudaEventCreateWithFlags(&eJoin, cudaEventDisableTiming);

    long nDD4 = (long)3 * Dc * Dc / 4;
    long nFF4 = (long)3 * DFFc * Dc / 4;
    long nX4  = (long)MROWS * Dc / 4;

    cudaEventRecord(eFork, 0);
    cudaStreamWaitEvent(s2, eFork, 0);

    // stream 0: k/v/o weights + qa embed
    round_copy3<<<dim3((unsigned)((nDD4 + 255) / 256), 3), 256>>>(
        kW, W.wk, vW, W.wv, oW, W.wo, nDD4);
    cudaEventRecord(eW, 0);
    round_copy_h<<<(int)((nX4 + 255) / 256), 256>>>(qa_embed, qa_h, nX4);
    cudaEventRecord(eQA, 0);

    // s2: FFN weights + q embed, then L0 v-prep
    round_copy2<<<dim3((unsigned)((nFF4 + 255) / 256), 2), 256, 0, s2>>>(
        w1, W.w1, w2, W.w2, nFF4);
    cudaEventRecord(eFF, s2);
    round_copy_h<<<(int)((nX4 + 255) / 256), 256, 0, s2>>>(q_embed, q_h, nX4);
    cudaStreamWaitEvent(s2, eW, 0);
    cudaStreamWaitEvent(s2, eQA, 0);
    vprep(qa_h, 0, vb, W, A, s2);
    cudaEventRecord(eV0, s2);

    // stream 0: layer 0 (q-chain, tail with FFN)
    qchain(qa_h, 0, 1, kb, gammas, alphas, gE, W, A, 0);
    cudaStreamWaitEvent(0, eV0, 0);
    cudaStreamWaitEvent(0, eFF, 0);
    tail(qa_embed, y, y_h, t1, t1_h, ff_h, 0, 1,
         ob, ln1g, ln1b, b1, b2, ln2g, ln2b, W, A, A, 0);
    cudaEventRecord(eY, 0);

    // s2: layer 1 complete (buffers B2)
    vprep(q_h, 1, vb, W, B2, s2);
    qchain(q_h, 1, 1, kb, gammas, alphas, gE, W, B2, s2);
    tail(q_embed, xb, xb_h, nullptr, nullptr, nullptr, 1, 0,
         ob, ln1g, ln1b, b1, b2, ln2g, ln2b, W, B2, B2, s2);

    // s2: layer 2 q-chain (needs xb_h only; reuses B2 after L1 done on same stream)
    qchain(xb_h, 2, 0, kb, gammas, alphas, gE, W, B2, s2);
    cudaEventRecord(eS2, s2);

    // s2: layer 2 v-prep into A (needs y_h; A.cat_h free after eY)
    cudaStreamWaitEvent(s2, eY, 0);
    vprep(y_h, 2, vb, W, A, s2);
    cudaEventRecord(eV2, s2);

    // stream 0: layer 2 tail (att@V: B2 probs x A.v -> B2.cat -> out)
    cudaStreamWaitEvent(0, eS2, 0);
    cudaStreamWaitEvent(0, eV2, 0);
    tail(xb, out, nullptr, t1, t1_h, ff_h, 2, 1,
         ob, ln1g, ln1b, b1, b2, ln2g, ln2b, W, B2, A, 0);

    cudaEventRecord(eJoin, s2);
    cudaStreamWaitEvent(0, eJoin, 0);
}